// round 12
// baseline (speedup 1.0000x reference)
#include <cuda_runtime.h>
#include <cuda_bf16.h>
#include <cstdint>

// Problem constants
#define B      2
#define S      4096      // 16*16*16
#define DIM    64
#define HEADS  4
#define DHEAD  32
#define HIDDEN (HEADS*DHEAD)   // 128
#define BH     (B*HEADS)       // 8
#define NROWS  (B*S)           // 8192
#define SCALE  16.0f
#define EPS    1e-5f
#define NSPLIT 2
#define SHALF  (S / NSPLIT)    // 2048 keys per split

// Scratch (no allocations allowed)
__device__ float g_q[BH * S * DHEAD];     // [bh][s][d]
__device__ float g_k[BH * S * DHEAD];
__device__ float g_v[BH * S * DHEAD];
__device__ float g_mean[2][BH][DHEAD];    // [0]=q, [1]=k
__device__ float g_rstd[2][BH][DHEAD];
__device__ float g_o[B * S * HIDDEN];     // [b][s][h][d]
__device__ float g_po[NSPLIT][BH * S * DHEAD];  // unnormalized partial O
__device__ float g_pl[NSPLIT][BH * S];          // partial softmax denom
__device__ float g_pm[NSPLIT][BH * S];          // partial running max

// ---------------------------------------------------------------------------
// helpers
// ---------------------------------------------------------------------------
__device__ __forceinline__ float tf32r(float x) {
    uint32_t u;
    asm("cvt.rna.tf32.f32 %0, %1;" : "=r"(u) : "f"(x));
    return __uint_as_float(u);
}

__device__ __forceinline__ void mma_tf32(float* d, const uint32_t* a,
                                         uint32_t b0, uint32_t b1,
                                         const float* c) {
    asm volatile(
        "mma.sync.aligned.m16n8k8.row.col.f32.tf32.tf32.f32 "
        "{%0,%1,%2,%3}, {%4,%5,%6,%7}, {%8,%9}, {%10,%11,%12,%13};\n"
        : "=f"(d[0]), "=f"(d[1]), "=f"(d[2]), "=f"(d[3])
        : "r"(a[0]), "r"(a[1]), "r"(a[2]), "r"(a[3]),
          "r"(b0), "r"(b1),
          "f"(c[0]), "f"(c[1]), "f"(c[2]), "f"(c[3]));
}

// ---------------------------------------------------------------------------
// K1: qkv = input @ w_qkv, 16 rows per block, weights register-resident.
// ---------------------------------------------------------------------------
#define QR 16
__global__ __launch_bounds__(384) void qkv_kernel(const float* __restrict__ inp,
                                                  const float* __restrict__ w_qkv) {
    __shared__ float sh[QR][DIM];
    int row0 = blockIdx.x * QR;
    int c    = threadIdx.x;          // 0..383
    for (int idx = c; idx < QR * DIM; idx += 384)
        sh[idx >> 6][idx & 63] = inp[(row0 + (idx >> 6)) * DIM + (idx & 63)];
    __syncthreads();

    float w[DIM];
#pragma unroll
    for (int k = 0; k < DIM; k++) w[k] = w_qkv[k * 384 + c];

    int part = c >> 7;               // 0=q, 1=k, 2=v
    int hc = c & 127;
    int h = hc >> 5, d = hc & 31;
    float* dst = (part == 0) ? g_q : (part == 1) ? g_k : g_v;
    int b = row0 >> 12;              // all 16 rows share b (16 | 4096)
    int s0 = row0 & 4095;
    float* base = dst + (((b * HEADS + h) * S) + s0) * DHEAD + d;

#pragma unroll
    for (int rr = 0; rr < QR; rr += 4) {
        float a0 = 0.f, a1 = 0.f, a2 = 0.f, a3 = 0.f;
#pragma unroll
        for (int k4 = 0; k4 < DIM / 4; k4++) {
            float4 s0v = *(const float4*)&sh[rr + 0][k4 * 4];
            float4 s1v = *(const float4*)&sh[rr + 1][k4 * 4];
            float4 s2v = *(const float4*)&sh[rr + 2][k4 * 4];
            float4 s3v = *(const float4*)&sh[rr + 3][k4 * 4];
            float w0 = w[k4 * 4], w1 = w[k4 * 4 + 1], w2 = w[k4 * 4 + 2], w3 = w[k4 * 4 + 3];
            a0 = fmaf(s0v.x, w0, a0); a0 = fmaf(s0v.y, w1, a0); a0 = fmaf(s0v.z, w2, a0); a0 = fmaf(s0v.w, w3, a0);
            a1 = fmaf(s1v.x, w0, a1); a1 = fmaf(s1v.y, w1, a1); a1 = fmaf(s1v.z, w2, a1); a1 = fmaf(s1v.w, w3, a1);
            a2 = fmaf(s2v.x, w0, a2); a2 = fmaf(s2v.y, w1, a2); a2 = fmaf(s2v.z, w2, a2); a2 = fmaf(s2v.w, w3, a2);
            a3 = fmaf(s3v.x, w0, a3); a3 = fmaf(s3v.y, w1, a3); a3 = fmaf(s3v.z, w2, a3); a3 = fmaf(s3v.w, w3, a3);
        }
        base[(rr + 0) * DHEAD] = a0;
        base[(rr + 1) * DHEAD] = a1;
        base[(rr + 2) * DHEAD] = a2;
        base[(rr + 3) * DHEAD] = a3;
    }
}

// ---------------------------------------------------------------------------
// K2: per-(b,h,d) mean / rstd over s for q and k.
// ---------------------------------------------------------------------------
__global__ void stats_kernel() {
    int bh = blockIdx.x;
    int qk = blockIdx.y;
    const float* src = ((qk == 0) ? g_q : g_k) + bh * S * DHEAD;
    int lane = threadIdx.x & 31;
    int warp = threadIdx.x >> 5;

    float sum = 0.f, ss = 0.f;
    for (int s = warp; s < S; s += 8) {
        float v = src[s * DHEAD + lane];
        sum += v;
        ss = fmaf(v, v, ss);
    }
    __shared__ float shs[8][32], shss[8][32];
    shs[warp][lane] = sum;
    shss[warp][lane] = ss;
    __syncthreads();
    if (warp == 0) {
        float t = 0.f, t2 = 0.f;
#pragma unroll
        for (int w = 0; w < 8; w++) { t += shs[w][lane]; t2 += shss[w][lane]; }
        float mean = t * (1.f / (float)S);
        float var  = t2 * (1.f / (float)S) - mean * mean;
        g_mean[qk][bh][lane] = mean;
        g_rstd[qk][bh][lane] = rsqrtf(var + EPS);
    }
}

// ---------------------------------------------------------------------------
// K3: flash attention, tf32 mma with 3xTF32-compensated QK^T.
// Split-KV x2: blockIdx.z selects key range [z*2048, (z+1)*2048).
// Block: 4 warps x 32 queries = 128 queries; key tiles of 64 as two halves.
// Writes unnormalized partial (O, l, m) for the merge kernel.
// ---------------------------------------------------------------------------
#define KT 64
#define KP 36
#define VP 40
#define PP 36
__global__ __launch_bounds__(128, 3) void attn_mma_kernel() {
    __shared__ float ksh[KT][KP];        // normalized K hi (tf32)
    __shared__ float kshl[KT][KP];       // normalized K lo residual (tf32)
    __shared__ float vsh[KT][VP];        // V (tf32)
    __shared__ float psh[4][32][PP];     // per-warp P (32 queries x 32 keys)
    __shared__ float kscale[DHEAD], kbias[DHEAD];

    int bh   = blockIdx.y;
    int z    = blockIdx.z;
    int tid  = threadIdx.x;
    int warp = tid >> 5;
    int lane = tid & 31;
    int gid  = lane >> 2;            // 0..7
    int tig  = lane & 3;             // 0..3

    const float* qp = g_q + bh * S * DHEAD;
    const float4* kp4 = (const float4*)(g_k + bh * S * DHEAD);
    const float4* vp4 = (const float4*)(g_v + bh * S * DHEAD);

    if (tid < DHEAD) {
        float mu = g_mean[1][bh][tid], rs = g_rstd[1][bh][tid];
        kscale[tid] = rs;
        kbias[tid]  = -mu * rs;
    }
    __syncthreads();

    // -------- Q fragments for two 16-row blocks (hi + lo) --------
    int q0 = blockIdx.x * 128 + warp * 32;
    uint32_t qf[2][4][4], qfl[2][4][4];
#pragma unroll
    for (int rb = 0; rb < 2; rb++) {
#pragma unroll
        for (int ks = 0; ks < 4; ks++) {
#pragma unroll
            for (int ci = 0; ci < 2; ci++) {
                int c = ks * 8 + tig + ci * 4;
                float mu = g_mean[0][bh][c], rs = g_rstd[0][bh][c] * SCALE;
                int r0 = q0 + rb * 16 + gid;
                float v0 = (qp[r0 * DHEAD + c] - mu) * rs;
                float v1 = (qp[(r0 + 8) * DHEAD + c] - mu) * rs;
                float h0 = tf32r(v0), h1 = tf32r(v1);
                qf[rb][ks][ci * 2 + 0]  = __float_as_uint(h0);
                qf[rb][ks][ci * 2 + 1]  = __float_as_uint(h1);
                qfl[rb][ks][ci * 2 + 0] = __float_as_uint(tf32r(v0 - h0));
                qfl[rb][ks][ci * 2 + 1] = __float_as_uint(tf32r(v1 - h1));
            }
        }
    }

    float oacc0[4][4], oacc1[4][4];
#pragma unroll
    for (int i = 0; i < 4; i++)
#pragma unroll
        for (int j = 0; j < 4; j++) { oacc0[i][j] = 0.f; oacc1[i][j] = 0.f; }
    float m0 = -1e30f, m1 = -1e30f, m2 = -1e30f, m3 = -1e30f;
    float l0 = 0.f, l1 = 0.f, l2 = 0.f, l3 = 0.f;

    int kend = (z + 1) * SHALF;
    for (int j0 = z * SHALF; j0 < kend; j0 += KT) {
        __syncthreads();
        const float4* kt4 = kp4 + ((j0 * DHEAD) >> 2);
        const float4* vt4 = vp4 + ((j0 * DHEAD) >> 2);
#pragma unroll
        for (int i = 0; i < 4; i++) {
            int idx = tid + i * 128;     // 0..511
            int j   = idx >> 3;
            int d4  = (idx & 7) * 4;
            float4 kk = kt4[idx];
            float4 vv = vt4[idx];
            float n0 = fmaf(kk.x, kscale[d4 + 0], kbias[d4 + 0]);
            float n1 = fmaf(kk.y, kscale[d4 + 1], kbias[d4 + 1]);
            float n2 = fmaf(kk.z, kscale[d4 + 2], kbias[d4 + 2]);
            float n3 = fmaf(kk.w, kscale[d4 + 3], kbias[d4 + 3]);
            float h0 = tf32r(n0), h1 = tf32r(n1), h2 = tf32r(n2), h3 = tf32r(n3);
            ksh[j][d4 + 0] = h0;  kshl[j][d4 + 0] = tf32r(n0 - h0);
            ksh[j][d4 + 1] = h1;  kshl[j][d4 + 1] = tf32r(n1 - h1);
            ksh[j][d4 + 2] = h2;  kshl[j][d4 + 2] = tf32r(n2 - h2);
            ksh[j][d4 + 3] = h3;  kshl[j][d4 + 3] = tf32r(n3 - h3);
            vsh[j][d4 + 0] = tf32r(vv.x);
            vsh[j][d4 + 1] = tf32r(vv.y);
            vsh[j][d4 + 2] = tf32r(vv.z);
            vsh[j][d4 + 3] = tf32r(vv.w);
        }
        __syncthreads();

#pragma unroll
        for (int hh = 0; hh < 2; hh++) {
            // -------- QK^T: 32x32 scores (two 16-row blocks), 3xTF32 ------
            float sc0[4][4], sc1[4][4];
#pragma unroll
            for (int nt = 0; nt < 4; nt++) {
#pragma unroll
                for (int j = 0; j < 4; j++) { sc0[nt][j] = 0.f; sc1[nt][j] = 0.f; }
#pragma unroll
                for (int ks = 0; ks < 4; ks++) {
                    int r = hh * 32 + nt * 8 + gid, c = ks * 8 + tig;
                    uint32_t bh0 = __float_as_uint(ksh[r][c]);
                    uint32_t bh1 = __float_as_uint(ksh[r][c + 4]);
                    uint32_t bl0 = __float_as_uint(kshl[r][c]);
                    uint32_t bl1 = __float_as_uint(kshl[r][c + 4]);
                    mma_tf32(sc0[nt], qf[0][ks],  bh0, bh1, sc0[nt]);
                    mma_tf32(sc0[nt], qf[0][ks],  bl0, bl1, sc0[nt]);
                    mma_tf32(sc0[nt], qfl[0][ks], bh0, bh1, sc0[nt]);
                    mma_tf32(sc1[nt], qf[1][ks],  bh0, bh1, sc1[nt]);
                    mma_tf32(sc1[nt], qf[1][ks],  bl0, bl1, sc1[nt]);
                    mma_tf32(sc1[nt], qfl[1][ks], bh0, bh1, sc1[nt]);
                }
            }

            // -------- online softmax (4 row groups) --------
            float tm0 = -1e30f, tm1 = -1e30f, tm2 = -1e30f, tm3 = -1e30f;
#pragma unroll
            for (int nt = 0; nt < 4; nt++) {
                tm0 = fmaxf(tm0, fmaxf(sc0[nt][0], sc0[nt][1]));
                tm1 = fmaxf(tm1, fmaxf(sc0[nt][2], sc0[nt][3]));
                tm2 = fmaxf(tm2, fmaxf(sc1[nt][0], sc1[nt][1]));
                tm3 = fmaxf(tm3, fmaxf(sc1[nt][2], sc1[nt][3]));
            }
            tm0 = fmaxf(tm0, __shfl_xor_sync(0xffffffffu, tm0, 1));
            tm0 = fmaxf(tm0, __shfl_xor_sync(0xffffffffu, tm0, 2));
            tm1 = fmaxf(tm1, __shfl_xor_sync(0xffffffffu, tm1, 1));
            tm1 = fmaxf(tm1, __shfl_xor_sync(0xffffffffu, tm1, 2));
            tm2 = fmaxf(tm2, __shfl_xor_sync(0xffffffffu, tm2, 1));
            tm2 = fmaxf(tm2, __shfl_xor_sync(0xffffffffu, tm2, 2));
            tm3 = fmaxf(tm3, __shfl_xor_sync(0xffffffffu, tm3, 1));
            tm3 = fmaxf(tm3, __shfl_xor_sync(0xffffffffu, tm3, 2));

            if (tm0 > m0) {
                float corr = __expf(m0 - tm0); m0 = tm0; l0 *= corr;
#pragma unroll
                for (int nt = 0; nt < 4; nt++) { oacc0[nt][0] *= corr; oacc0[nt][1] *= corr; }
            }
            if (tm1 > m1) {
                float corr = __expf(m1 - tm1); m1 = tm1; l1 *= corr;
#pragma unroll
                for (int nt = 0; nt < 4; nt++) { oacc0[nt][2] *= corr; oacc0[nt][3] *= corr; }
            }
            if (tm2 > m2) {
                float corr = __expf(m2 - tm2); m2 = tm2; l2 *= corr;
#pragma unroll
                for (int nt = 0; nt < 4; nt++) { oacc1[nt][0] *= corr; oacc1[nt][1] *= corr; }
            }
            if (tm3 > m3) {
                float corr = __expf(m3 - tm3); m3 = tm3; l3 *= corr;
#pragma unroll
                for (int nt = 0; nt < 4; nt++) { oacc1[nt][2] *= corr; oacc1[nt][3] *= corr; }
            }

#pragma unroll
            for (int nt = 0; nt < 4; nt++) {
                float p0 = tf32r(__expf(sc0[nt][0] - m0));
                float p1 = tf32r(__expf(sc0[nt][1] - m0));
                float p2 = tf32r(__expf(sc0[nt][2] - m1));
                float p3 = tf32r(__expf(sc0[nt][3] - m1));
                l0 += p0 + p1; l1 += p2 + p3;
                *(float2*)&psh[warp][gid][nt * 8 + 2 * tig]      = make_float2(p0, p1);
                *(float2*)&psh[warp][gid + 8][nt * 8 + 2 * tig]  = make_float2(p2, p3);
                float p4 = tf32r(__expf(sc1[nt][0] - m2));
                float p5 = tf32r(__expf(sc1[nt][1] - m2));
                float p6 = tf32r(__expf(sc1[nt][2] - m3));
                float p7 = tf32r(__expf(sc1[nt][3] - m3));
                l2 += p4 + p5; l3 += p6 + p7;
                *(float2*)&psh[warp][gid + 16][nt * 8 + 2 * tig] = make_float2(p4, p5);
                *(float2*)&psh[warp][gid + 24][nt * 8 + 2 * tig] = make_float2(p6, p7);
            }
            __syncwarp();

            // -------- P @ V : 32 keys of this half --------
#pragma unroll
            for (int ks2 = 0; ks2 < 4; ks2++) {
                uint32_t a0[4], a1[4];
                a0[0] = __float_as_uint(psh[warp][gid][ks2 * 8 + tig]);
                a0[1] = __float_as_uint(psh[warp][gid + 8][ks2 * 8 + tig]);
                a0[2] = __float_as_uint(psh[warp][gid][ks2 * 8 + tig + 4]);
                a0[3] = __float_as_uint(psh[warp][gid + 8][ks2 * 8 + tig + 4]);
                a1[0] = __float_as_uint(psh[warp][gid + 16][ks2 * 8 + tig]);
                a1[1] = __float_as_uint(psh[warp][gid + 24][ks2 * 8 + tig]);
                a1[2] = __float_as_uint(psh[warp][gid + 16][ks2 * 8 + tig + 4]);
                a1[3] = __float_as_uint(psh[warp][gid + 24][ks2 * 8 + tig + 4]);
                int vr = hh * 32 + ks2 * 8 + tig;
#pragma unroll
                for (int nt2 = 0; nt2 < 4; nt2++) {
                    uint32_t b0 = __float_as_uint(vsh[vr][nt2 * 8 + gid]);
                    uint32_t b1 = __float_as_uint(vsh[vr + 4][nt2 * 8 + gid]);
                    mma_tf32(oacc0[nt2], a0, b0, b1, oacc0[nt2]);
                    mma_tf32(oacc1[nt2], a1, b0, b1, oacc1[nt2]);
                }
            }
            __syncwarp();
        }
    }

    // -------- reduce denominators across the 4-lane group --------
    l0 += __shfl_xor_sync(0xffffffffu, l0, 1);
    l0 += __shfl_xor_sync(0xffffffffu, l0, 2);
    l1 += __shfl_xor_sync(0xffffffffu, l1, 1);
    l1 += __shfl_xor_sync(0xffffffffu, l1, 2);
    l2 += __shfl_xor_sync(0xffffffffu, l2, 1);
    l2 += __shfl_xor_sync(0xffffffffu, l2, 2);
    l3 += __shfl_xor_sync(0xffffffffu, l3, 1);
    l3 += __shfl_xor_sync(0xffffffffu, l3, 2);

    // -------- write unnormalized partials --------
    int r0 = q0 + gid;
    float* pbase = g_po[z] + bh * S * DHEAD;
    float* pp0 = pbase + (r0)      * DHEAD;
    float* pp1 = pbase + (r0 + 8)  * DHEAD;
    float* pp2 = pbase + (r0 + 16) * DHEAD;
    float* pp3 = pbase + (r0 + 24) * DHEAD;
#pragma unroll
    for (int nt2 = 0; nt2 < 4; nt2++) {
        int c = nt2 * 8 + 2 * tig;
        *(float2*)(pp0 + c) = make_float2(oacc0[nt2][0], oacc0[nt2][1]);
        *(float2*)(pp1 + c) = make_float2(oacc0[nt2][2], oacc0[nt2][3]);
        *(float2*)(pp2 + c) = make_float2(oacc1[nt2][0], oacc1[nt2][1]);
        *(float2*)(pp3 + c) = make_float2(oacc1[nt2][2], oacc1[nt2][3]);
    }
    if (tig == 0) {
        int rsb = bh * S + r0;
        g_pl[z][rsb]      = l0;  g_pm[z][rsb]      = m0;
        g_pl[z][rsb + 8]  = l1;  g_pm[z][rsb + 8]  = m1;
        g_pl[z][rsb + 16] = l2;  g_pm[z][rsb + 16] = m2;
        g_pl[z][rsb + 24] = l3;  g_pm[z][rsb + 24] = m3;
    }
}

// ---------------------------------------------------------------------------
// K3b: merge the two split-KV partials into g_o.
// ---------------------------------------------------------------------------
__global__ __launch_bounds__(256) void merge_kernel() {
    int t  = blockIdx.x * 256 + threadIdx.x;   // 0 .. BH*S*DHEAD-1
    int d  = t & (DHEAD - 1);
    int rs = t >> 5;                            // bh*S + s
    float m0 = g_pm[0][rs], m1 = g_pm[1][rs];
    float l0 = g_pl[0][rs], l1 = g_pl[1][rs];
    float mx = fmaxf(m0, m1);
    float w0 = __expf(m0 - mx), w1 = __expf(m1 - mx);
    float o  = g_po[0][t] * w0 + g_po[1][t] * w1;
    float inv = 1.f / (l0 * w0 + l1 * w1);
    int bh = rs >> 12, s = rs & (S - 1);
    int b = bh >> 2, h = bh & 3;
    g_o[((b * S + s) * HEADS + h) * DHEAD + d] = o * inv;
}

// ---------------------------------------------------------------------------
// K4: out = o @ w_out + b_out
// ---------------------------------------------------------------------------
__global__ void out_kernel(const float* __restrict__ w_out,
                           const float* __restrict__ b_out,
                           float* __restrict__ out) {
    __shared__ float sh[HIDDEN];
    int row = blockIdx.x;
    int c   = threadIdx.x;           // 0..63
    sh[c]       = g_o[row * HIDDEN + c];
    sh[c + 64]  = g_o[row * HIDDEN + 64 + c];
    __syncthreads();

    float acc = b_out[c];
#pragma unroll
    for (int k = 0; k < HIDDEN; k++)
        acc = fmaf(sh[k], w_out[k * DIM + c], acc);
    out[row * DIM + c] = acc;
}

// ---------------------------------------------------------------------------
extern "C" void kernel_launch(void* const* d_in, const int* in_sizes, int n_in,
                              void* d_out, int out_size) {
    const float* inp   = (const float*)d_in[0];
    const float* w_qkv = (const float*)d_in[1];
    const float* w_out = (const float*)d_in[2];
    const float* b_out = (const float*)d_in[3];
    float* out = (float*)d_out;

    qkv_kernel<<<NROWS / QR, 384>>>(inp, w_qkv);
    stats_kernel<<<dim3(BH, 2), 256>>>();
    attn_mma_kernel<<<dim3(S / 128, BH, NSPLIT), 128>>>();
    merge_kernel<<<(BH * S * DHEAD) / 256, 256>>>();
    out_kernel<<<NROWS, 64>>>(w_out, b_out, out);
}

// round 13
// speedup vs baseline: 1.0790x; 1.0790x over previous
#include <cuda_runtime.h>
#include <cuda_bf16.h>
#include <cstdint>

// Problem constants
#define B      2
#define S      4096      // 16*16*16
#define DIM    64
#define HEADS  4
#define DHEAD  32
#define HIDDEN (HEADS*DHEAD)   // 128
#define BH     (B*HEADS)       // 8
#define NROWS  (B*S)           // 8192
#define SCALE  16.0f
#define EPS    1e-5f

// Scratch (no allocations allowed)
__device__ float g_q[BH * S * DHEAD];     // [bh][s][d]
__device__ float g_k[BH * S * DHEAD];
__device__ float g_v[BH * S * DHEAD];
__device__ float g_mean[2][BH][DHEAD];    // [0]=q, [1]=k
__device__ float g_rstd[2][BH][DHEAD];
__device__ float g_o[B * S * HIDDEN];     // [b][s][h][d]

// ---------------------------------------------------------------------------
// helpers
// ---------------------------------------------------------------------------
__device__ __forceinline__ float tf32r(float x) {
    uint32_t u;
    asm("cvt.rna.tf32.f32 %0, %1;" : "=r"(u) : "f"(x));
    return __uint_as_float(u);
}

__device__ __forceinline__ void mma_tf32(float* d, const uint32_t* a,
                                         uint32_t b0, uint32_t b1,
                                         const float* c) {
    asm volatile(
        "mma.sync.aligned.m16n8k8.row.col.f32.tf32.tf32.f32 "
        "{%0,%1,%2,%3}, {%4,%5,%6,%7}, {%8,%9}, {%10,%11,%12,%13};\n"
        : "=f"(d[0]), "=f"(d[1]), "=f"(d[2]), "=f"(d[3])
        : "r"(a[0]), "r"(a[1]), "r"(a[2]), "r"(a[3]),
          "r"(b0), "r"(b1),
          "f"(c[0]), "f"(c[1]), "f"(c[2]), "f"(c[3]));
}

// ---------------------------------------------------------------------------
// K1: qkv = input @ w_qkv, 16 rows per block, weights register-resident.
// ---------------------------------------------------------------------------
#define QR 16
__global__ __launch_bounds__(384) void qkv_kernel(const float* __restrict__ inp,
                                                  const float* __restrict__ w_qkv) {
    __shared__ float sh[QR][DIM];
    int row0 = blockIdx.x * QR;
    int c    = threadIdx.x;          // 0..383
    for (int idx = c; idx < QR * DIM; idx += 384)
        sh[idx >> 6][idx & 63] = inp[(row0 + (idx >> 6)) * DIM + (idx & 63)];
    __syncthreads();

    float w[DIM];
#pragma unroll
    for (int k = 0; k < DIM; k++) w[k] = w_qkv[k * 384 + c];

    int part = c >> 7;               // 0=q, 1=k, 2=v
    int hc = c & 127;
    int h = hc >> 5, d = hc & 31;
    float* dst = (part == 0) ? g_q : (part == 1) ? g_k : g_v;
    int b = row0 >> 12;              // all 16 rows share b (16 | 4096)
    int s0 = row0 & 4095;
    float* base = dst + (((b * HEADS + h) * S) + s0) * DHEAD + d;

#pragma unroll
    for (int rr = 0; rr < QR; rr += 4) {
        float a0 = 0.f, a1 = 0.f, a2 = 0.f, a3 = 0.f;
#pragma unroll
        for (int k4 = 0; k4 < DIM / 4; k4++) {
            float4 s0v = *(const float4*)&sh[rr + 0][k4 * 4];
            float4 s1v = *(const float4*)&sh[rr + 1][k4 * 4];
            float4 s2v = *(const float4*)&sh[rr + 2][k4 * 4];
            float4 s3v = *(const float4*)&sh[rr + 3][k4 * 4];
            float w0 = w[k4 * 4], w1 = w[k4 * 4 + 1], w2 = w[k4 * 4 + 2], w3 = w[k4 * 4 + 3];
            a0 = fmaf(s0v.x, w0, a0); a0 = fmaf(s0v.y, w1, a0); a0 = fmaf(s0v.z, w2, a0); a0 = fmaf(s0v.w, w3, a0);
            a1 = fmaf(s1v.x, w0, a1); a1 = fmaf(s1v.y, w1, a1); a1 = fmaf(s1v.z, w2, a1); a1 = fmaf(s1v.w, w3, a1);
            a2 = fmaf(s2v.x, w0, a2); a2 = fmaf(s2v.y, w1, a2); a2 = fmaf(s2v.z, w2, a2); a2 = fmaf(s2v.w, w3, a2);
            a3 = fmaf(s3v.x, w0, a3); a3 = fmaf(s3v.y, w1, a3); a3 = fmaf(s3v.z, w2, a3); a3 = fmaf(s3v.w, w3, a3);
        }
        base[(rr + 0) * DHEAD] = a0;
        base[(rr + 1) * DHEAD] = a1;
        base[(rr + 2) * DHEAD] = a2;
        base[(rr + 3) * DHEAD] = a3;
    }
}

// ---------------------------------------------------------------------------
// K2: per-(b,h,d) mean / rstd over s for q and k.
// ---------------------------------------------------------------------------
__global__ void stats_kernel() {
    int bh = blockIdx.x;
    int qk = blockIdx.y;
    const float* src = ((qk == 0) ? g_q : g_k) + bh * S * DHEAD;
    int lane = threadIdx.x & 31;
    int warp = threadIdx.x >> 5;

    float sum = 0.f, ss = 0.f;
    for (int s = warp; s < S; s += 8) {
        float v = src[s * DHEAD + lane];
        sum += v;
        ss = fmaf(v, v, ss);
    }
    __shared__ float shs[8][32], shss[8][32];
    shs[warp][lane] = sum;
    shss[warp][lane] = ss;
    __syncthreads();
    if (warp == 0) {
        float t = 0.f, t2 = 0.f;
#pragma unroll
        for (int w = 0; w < 8; w++) { t += shs[w][lane]; t2 += shss[w][lane]; }
        float mean = t * (1.f / (float)S);
        float var  = t2 * (1.f / (float)S) - mean * mean;
        g_mean[qk][bh][lane] = mean;
        g_rstd[qk][bh][lane] = rsqrtf(var + EPS);
    }
}

// ---------------------------------------------------------------------------
// K3: flash attention, tf32 mma with 3xTF32-compensated QK^T (round-10 form).
// Block: 4 warps x 32 queries = 128 queries. Key tiles of 64, two halves.
// Register double-buffered global loads; vsh pitch 40.
// ---------------------------------------------------------------------------
#define KT 64
#define KP 36
#define VP 40
#define PP 36
__global__ __launch_bounds__(128) void attn_mma_kernel() {
    __shared__ float ksh[KT][KP];        // normalized K hi (tf32)
    __shared__ float kshl[KT][KP];       // normalized K lo residual (tf32)
    __shared__ float vsh[KT][VP];        // V (tf32)
    __shared__ float psh[4][32][PP];     // per-warp P (32 queries x 32 keys)
    __shared__ float kscale[DHEAD], kbias[DHEAD];

    int bh   = blockIdx.y;
    int tid  = threadIdx.x;
    int warp = tid >> 5;
    int lane = tid & 31;
    int gid  = lane >> 2;            // 0..7
    int tig  = lane & 3;             // 0..3

    const float* qp = g_q + bh * S * DHEAD;
    const float* kp = g_k + bh * S * DHEAD;
    const float* vp = g_v + bh * S * DHEAD;
    const float4* kp4 = (const float4*)kp;
    const float4* vp4 = (const float4*)vp;

    if (tid < DHEAD) {
        float mu = g_mean[1][bh][tid], rs = g_rstd[1][bh][tid];
        kscale[tid] = rs;
        kbias[tid]  = -mu * rs;
    }
    __syncthreads();

    // -------- Q fragments for two 16-row blocks (hi + lo) --------
    int q0 = blockIdx.x * 128 + warp * 32;
    uint32_t qf[2][4][4], qfl[2][4][4];
#pragma unroll
    for (int rb = 0; rb < 2; rb++) {
#pragma unroll
        for (int ks = 0; ks < 4; ks++) {
#pragma unroll
            for (int ci = 0; ci < 2; ci++) {
                int c = ks * 8 + tig + ci * 4;
                float mu = g_mean[0][bh][c], rs = g_rstd[0][bh][c] * SCALE;
                int r0 = q0 + rb * 16 + gid;
                float v0 = (qp[r0 * DHEAD + c] - mu) * rs;
                float v1 = (qp[(r0 + 8) * DHEAD + c] - mu) * rs;
                float h0 = tf32r(v0), h1 = tf32r(v1);
                qf[rb][ks][ci * 2 + 0]  = __float_as_uint(h0);
                qf[rb][ks][ci * 2 + 1]  = __float_as_uint(h1);
                qfl[rb][ks][ci * 2 + 0] = __float_as_uint(tf32r(v0 - h0));
                qfl[rb][ks][ci * 2 + 1] = __float_as_uint(tf32r(v1 - h1));
            }
        }
    }

    float oacc0[4][4], oacc1[4][4];
#pragma unroll
    for (int i = 0; i < 4; i++)
#pragma unroll
        for (int j = 0; j < 4; j++) { oacc0[i][j] = 0.f; oacc1[i][j] = 0.f; }
    float m0 = -1e30f, m1 = -1e30f, m2 = -1e30f, m3 = -1e30f;
    float l0 = 0.f, l1 = 0.f, l2 = 0.f, l3 = 0.f;

    // -------- prologue: load tile 0 into registers --------
    float4 kreg[4], vreg[4];
#pragma unroll
    for (int i = 0; i < 4; i++) {
        kreg[i] = kp4[tid + i * 128];
        vreg[i] = vp4[tid + i * 128];
    }

    for (int j0 = 0; j0 < S; j0 += KT) {
        __syncthreads();
        // convert + store the registers holding tile j0
#pragma unroll
        for (int i = 0; i < 4; i++) {
            int idx = tid + i * 128;     // 0..511
            int j   = idx >> 3;
            int d4  = (idx & 7) * 4;
            float4 kk = kreg[i];
            float4 vv = vreg[i];
            float n0 = fmaf(kk.x, kscale[d4 + 0], kbias[d4 + 0]);
            float n1 = fmaf(kk.y, kscale[d4 + 1], kbias[d4 + 1]);
            float n2 = fmaf(kk.z, kscale[d4 + 2], kbias[d4 + 2]);
            float n3 = fmaf(kk.w, kscale[d4 + 3], kbias[d4 + 3]);
            float h0 = tf32r(n0), h1 = tf32r(n1), h2 = tf32r(n2), h3 = tf32r(n3);
            ksh[j][d4 + 0] = h0;  kshl[j][d4 + 0] = tf32r(n0 - h0);
            ksh[j][d4 + 1] = h1;  kshl[j][d4 + 1] = tf32r(n1 - h1);
            ksh[j][d4 + 2] = h2;  kshl[j][d4 + 2] = tf32r(n2 - h2);
            ksh[j][d4 + 3] = h3;  kshl[j][d4 + 3] = tf32r(n3 - h3);
            vsh[j][d4 + 0] = tf32r(vv.x);
            vsh[j][d4 + 1] = tf32r(vv.y);
            vsh[j][d4 + 2] = tf32r(vv.z);
            vsh[j][d4 + 3] = tf32r(vv.w);
        }
        __syncthreads();

        // issue next tile's loads now — they complete during compute below
        if (j0 + KT < S) {
            int base4 = ((j0 + KT) * DHEAD) >> 2;
#pragma unroll
            for (int i = 0; i < 4; i++) {
                kreg[i] = kp4[base4 + tid + i * 128];
                vreg[i] = vp4[base4 + tid + i * 128];
            }
        }

#pragma unroll
        for (int hh = 0; hh < 2; hh++) {
            // -------- QK^T: 32x32 scores (two 16-row blocks), 3xTF32 ------
            float sc0[4][4], sc1[4][4];
#pragma unroll
            for (int nt = 0; nt < 4; nt++) {
#pragma unroll
                for (int j = 0; j < 4; j++) { sc0[nt][j] = 0.f; sc1[nt][j] = 0.f; }
#pragma unroll
                for (int ks = 0; ks < 4; ks++) {
                    int r = hh * 32 + nt * 8 + gid, c = ks * 8 + tig;
                    uint32_t bh0 = __float_as_uint(ksh[r][c]);
                    uint32_t bh1 = __float_as_uint(ksh[r][c + 4]);
                    uint32_t bl0 = __float_as_uint(kshl[r][c]);
                    uint32_t bl1 = __float_as_uint(kshl[r][c + 4]);
                    mma_tf32(sc0[nt], qf[0][ks],  bh0, bh1, sc0[nt]);
                    mma_tf32(sc0[nt], qf[0][ks],  bl0, bl1, sc0[nt]);
                    mma_tf32(sc0[nt], qfl[0][ks], bh0, bh1, sc0[nt]);
                    mma_tf32(sc1[nt], qf[1][ks],  bh0, bh1, sc1[nt]);
                    mma_tf32(sc1[nt], qf[1][ks],  bl0, bl1, sc1[nt]);
                    mma_tf32(sc1[nt], qfl[1][ks], bh0, bh1, sc1[nt]);
                }
            }

            // -------- online softmax (4 row groups) --------
            float tm0 = -1e30f, tm1 = -1e30f, tm2 = -1e30f, tm3 = -1e30f;
#pragma unroll
            for (int nt = 0; nt < 4; nt++) {
                tm0 = fmaxf(tm0, fmaxf(sc0[nt][0], sc0[nt][1]));
                tm1 = fmaxf(tm1, fmaxf(sc0[nt][2], sc0[nt][3]));
                tm2 = fmaxf(tm2, fmaxf(sc1[nt][0], sc1[nt][1]));
                tm3 = fmaxf(tm3, fmaxf(sc1[nt][2], sc1[nt][3]));
            }
            tm0 = fmaxf(tm0, __shfl_xor_sync(0xffffffffu, tm0, 1));
            tm0 = fmaxf(tm0, __shfl_xor_sync(0xffffffffu, tm0, 2));
            tm1 = fmaxf(tm1, __shfl_xor_sync(0xffffffffu, tm1, 1));
            tm1 = fmaxf(tm1, __shfl_xor_sync(0xffffffffu, tm1, 2));
            tm2 = fmaxf(tm2, __shfl_xor_sync(0xffffffffu, tm2, 1));
            tm2 = fmaxf(tm2, __shfl_xor_sync(0xffffffffu, tm2, 2));
            tm3 = fmaxf(tm3, __shfl_xor_sync(0xffffffffu, tm3, 1));
            tm3 = fmaxf(tm3, __shfl_xor_sync(0xffffffffu, tm3, 2));

            if (tm0 > m0) {
                float corr = __expf(m0 - tm0); m0 = tm0; l0 *= corr;
#pragma unroll
                for (int nt = 0; nt < 4; nt++) { oacc0[nt][0] *= corr; oacc0[nt][1] *= corr; }
            }
            if (tm1 > m1) {
                float corr = __expf(m1 - tm1); m1 = tm1; l1 *= corr;
#pragma unroll
                for (int nt = 0; nt < 4; nt++) { oacc0[nt][2] *= corr; oacc0[nt][3] *= corr; }
            }
            if (tm2 > m2) {
                float corr = __expf(m2 - tm2); m2 = tm2; l2 *= corr;
#pragma unroll
                for (int nt = 0; nt < 4; nt++) { oacc1[nt][0] *= corr; oacc1[nt][1] *= corr; }
            }
            if (tm3 > m3) {
                float corr = __expf(m3 - tm3); m3 = tm3; l3 *= corr;
#pragma unroll
                for (int nt = 0; nt < 4; nt++) { oacc1[nt][2] *= corr; oacc1[nt][3] *= corr; }
            }

#pragma unroll
            for (int nt = 0; nt < 4; nt++) {
                float p0 = tf32r(__expf(sc0[nt][0] - m0));
                float p1 = tf32r(__expf(sc0[nt][1] - m0));
                float p2 = tf32r(__expf(sc0[nt][2] - m1));
                float p3 = tf32r(__expf(sc0[nt][3] - m1));
                l0 += p0 + p1; l1 += p2 + p3;
                *(float2*)&psh[warp][gid][nt * 8 + 2 * tig]      = make_float2(p0, p1);
                *(float2*)&psh[warp][gid + 8][nt * 8 + 2 * tig]  = make_float2(p2, p3);
                float p4 = tf32r(__expf(sc1[nt][0] - m2));
                float p5 = tf32r(__expf(sc1[nt][1] - m2));
                float p6 = tf32r(__expf(sc1[nt][2] - m3));
                float p7 = tf32r(__expf(sc1[nt][3] - m3));
                l2 += p4 + p5; l3 += p6 + p7;
                *(float2*)&psh[warp][gid + 16][nt * 8 + 2 * tig] = make_float2(p4, p5);
                *(float2*)&psh[warp][gid + 24][nt * 8 + 2 * tig] = make_float2(p6, p7);
            }
            __syncwarp();

            // -------- P @ V : 32 keys of this half --------
#pragma unroll
            for (int ks2 = 0; ks2 < 4; ks2++) {
                uint32_t a0[4], a1[4];
                a0[0] = __float_as_uint(psh[warp][gid][ks2 * 8 + tig]);
                a0[1] = __float_as_uint(psh[warp][gid + 8][ks2 * 8 + tig]);
                a0[2] = __float_as_uint(psh[warp][gid][ks2 * 8 + tig + 4]);
                a0[3] = __float_as_uint(psh[warp][gid + 8][ks2 * 8 + tig + 4]);
                a1[0] = __float_as_uint(psh[warp][gid + 16][ks2 * 8 + tig]);
                a1[1] = __float_as_uint(psh[warp][gid + 24][ks2 * 8 + tig]);
                a1[2] = __float_as_uint(psh[warp][gid + 16][ks2 * 8 + tig + 4]);
                a1[3] = __float_as_uint(psh[warp][gid + 24][ks2 * 8 + tig + 4]);
                int vr = hh * 32 + ks2 * 8 + tig;
#pragma unroll
                for (int nt2 = 0; nt2 < 4; nt2++) {
                    uint32_t b0 = __float_as_uint(vsh[vr][nt2 * 8 + gid]);
                    uint32_t b1 = __float_as_uint(vsh[vr + 4][nt2 * 8 + gid]);
                    mma_tf32(oacc0[nt2], a0, b0, b1, oacc0[nt2]);
                    mma_tf32(oacc1[nt2], a1, b0, b1, oacc1[nt2]);
                }
            }
            __syncwarp();
        }
    }

    // -------- reduce denominators across the 4-lane group --------
    l0 += __shfl_xor_sync(0xffffffffu, l0, 1);
    l0 += __shfl_xor_sync(0xffffffffu, l0, 2);
    l1 += __shfl_xor_sync(0xffffffffu, l1, 1);
    l1 += __shfl_xor_sync(0xffffffffu, l1, 2);
    l2 += __shfl_xor_sync(0xffffffffu, l2, 1);
    l2 += __shfl_xor_sync(0xffffffffu, l2, 2);
    l3 += __shfl_xor_sync(0xffffffffu, l3, 1);
    l3 += __shfl_xor_sync(0xffffffffu, l3, 2);

    // -------- epilogue --------
    float inv0 = 1.f / l0, inv1 = 1.f / l1, inv2 = 1.f / l2, inv3 = 1.f / l3;
    int bb = bh >> 2, h = bh & 3;
    float* op0 = g_o + ((bb * S + q0 + gid)      * HEADS + h) * DHEAD;
    float* op1 = g_o + ((bb * S + q0 + gid + 8)  * HEADS + h) * DHEAD;
    float* op2 = g_o + ((bb * S + q0 + gid + 16) * HEADS + h) * DHEAD;
    float* op3 = g_o + ((bb * S + q0 + gid + 24) * HEADS + h) * DHEAD;
#pragma unroll
    for (int nt2 = 0; nt2 < 4; nt2++) {
        int c = nt2 * 8 + 2 * tig;
        *(float2*)(op0 + c) = make_float2(oacc0[nt2][0] * inv0, oacc0[nt2][1] * inv0);
        *(float2*)(op1 + c) = make_float2(oacc0[nt2][2] * inv1, oacc0[nt2][3] * inv1);
        *(float2*)(op2 + c) = make_float2(oacc1[nt2][0] * inv2, oacc1[nt2][1] * inv2);
        *(float2*)(op3 + c) = make_float2(oacc1[nt2][2] * inv3, oacc1[nt2][3] * inv3);
    }
}

// ---------------------------------------------------------------------------
// K4: out = o @ w_out + b_out  (round-10 version)
// ---------------------------------------------------------------------------
__global__ void out_kernel(const float* __restrict__ w_out,
                           const float* __restrict__ b_out,
                           float* __restrict__ out) {
    __shared__ float sh[HIDDEN];
    int row = blockIdx.x;
    int c   = threadIdx.x;           // 0..63
    sh[c]       = g_o[row * HIDDEN + c];
    sh[c + 64]  = g_o[row * HIDDEN + 64 + c];
    __syncthreads();

    float acc = b_out[c];
#pragma unroll
    for (int k = 0; k < HIDDEN; k++)
        acc = fmaf(sh[k], w_out[k * DIM + c], acc);
    out[row * DIM + c] = acc;
}

// ---------------------------------------------------------------------------
extern "C" void kernel_launch(void* const* d_in, const int* in_sizes, int n_in,
                              void* d_out, int out_size) {
    const float* inp   = (const float*)d_in[0];
    const float* w_qkv = (const float*)d_in[1];
    const float* w_out = (const float*)d_in[2];
    const float* b_out = (const float*)d_in[3];
    float* out = (float*)d_out;

    qkv_kernel<<<NROWS / QR, 384>>>(inp, w_qkv);
    stats_kernel<<<dim3(BH, 2), 256>>>();
    attn_mma_kernel<<<dim3(S / 128, BH), 128>>>();
    out_kernel<<<NROWS, 64>>>(w_out, b_out, out);
}

// round 14
// speedup vs baseline: 1.3294x; 1.2321x over previous
#include <cuda_runtime.h>
#include <cuda_bf16.h>
#include <cstdint>

// Problem constants
#define B      2
#define S      4096      // 16*16*16
#define DIM    64
#define HEADS  4
#define DHEAD  32
#define HIDDEN (HEADS*DHEAD)   // 128
#define BH     (B*HEADS)       // 8
#define NROWS  (B*S)           // 8192
#define SCALE  16.0f
#define EPS    1e-5f

// Scratch (no allocations allowed)
__device__ float g_q[BH * S * DHEAD];     // [bh][s][d]
__device__ float g_k[BH * S * DHEAD];
__device__ float g_v[BH * S * DHEAD];
__device__ float g_mean[2][BH][DHEAD];    // [0]=q, [1]=k
__device__ float g_rstd[2][BH][DHEAD];
__device__ float g_o[B * S * HIDDEN];     // [b][s][h][d]

// ---------------------------------------------------------------------------
// helpers
// ---------------------------------------------------------------------------
__device__ __forceinline__ float tf32r(float x) {
    uint32_t u;
    asm("cvt.rna.tf32.f32 %0, %1;" : "=r"(u) : "f"(x));
    return __uint_as_float(u);
}

// pack two floats to bf16x2: 'lo' -> lower 16 bits, 'hi' -> upper 16 bits
__device__ __forceinline__ uint32_t bf16x2_rn(float lo, float hi) {
    uint32_t r;
    asm("cvt.rn.bf16x2.f32 %0, %1, %2;" : "=r"(r) : "f"(hi), "f"(lo));
    return r;
}
__device__ __forceinline__ float bf_lo_f(uint32_t p) { return __uint_as_float(p << 16); }
__device__ __forceinline__ float bf_hi_f(uint32_t p) { return __uint_as_float(p & 0xffff0000u); }

__device__ __forceinline__ void mma_tf32(float* d, const uint32_t* a,
                                         uint32_t b0, uint32_t b1,
                                         const float* c) {
    asm volatile(
        "mma.sync.aligned.m16n8k8.row.col.f32.tf32.tf32.f32 "
        "{%0,%1,%2,%3}, {%4,%5,%6,%7}, {%8,%9}, {%10,%11,%12,%13};\n"
        : "=f"(d[0]), "=f"(d[1]), "=f"(d[2]), "=f"(d[3])
        : "r"(a[0]), "r"(a[1]), "r"(a[2]), "r"(a[3]),
          "r"(b0), "r"(b1),
          "f"(c[0]), "f"(c[1]), "f"(c[2]), "f"(c[3]));
}

__device__ __forceinline__ void mma_bf16(float* d, const uint32_t* a,
                                         uint32_t b0, uint32_t b1,
                                         const float* c) {
    asm volatile(
        "mma.sync.aligned.m16n8k16.row.col.f32.bf16.bf16.f32 "
        "{%0,%1,%2,%3}, {%4,%5,%6,%7}, {%8,%9}, {%10,%11,%12,%13};\n"
        : "=f"(d[0]), "=f"(d[1]), "=f"(d[2]), "=f"(d[3])
        : "r"(a[0]), "r"(a[1]), "r"(a[2]), "r"(a[3]),
          "r"(b0), "r"(b1),
          "f"(c[0]), "f"(c[1]), "f"(c[2]), "f"(c[3]));
}

// ---------------------------------------------------------------------------
// K1: qkv = input @ w_qkv, 16 rows per block, weights register-resident.
// ---------------------------------------------------------------------------
#define QR 16
__global__ __launch_bounds__(384) void qkv_kernel(const float* __restrict__ inp,
                                                  const float* __restrict__ w_qkv) {
    __shared__ float sh[QR][DIM];
    int row0 = blockIdx.x * QR;
    int c    = threadIdx.x;          // 0..383
    for (int idx = c; idx < QR * DIM; idx += 384)
        sh[idx >> 6][idx & 63] = inp[(row0 + (idx >> 6)) * DIM + (idx & 63)];
    __syncthreads();

    float w[DIM];
#pragma unroll
    for (int k = 0; k < DIM; k++) w[k] = w_qkv[k * 384 + c];

    int part = c >> 7;               // 0=q, 1=k, 2=v
    int hc = c & 127;
    int h = hc >> 5, d = hc & 31;
    float* dst = (part == 0) ? g_q : (part == 1) ? g_k : g_v;
    int b = row0 >> 12;              // all 16 rows share b (16 | 4096)
    int s0 = row0 & 4095;
    float* base = dst + (((b * HEADS + h) * S) + s0) * DHEAD + d;

#pragma unroll
    for (int rr = 0; rr < QR; rr += 4) {
        float a0 = 0.f, a1 = 0.f, a2 = 0.f, a3 = 0.f;
#pragma unroll
        for (int k4 = 0; k4 < DIM / 4; k4++) {
            float4 s0v = *(const float4*)&sh[rr + 0][k4 * 4];
            float4 s1v = *(const float4*)&sh[rr + 1][k4 * 4];
            float4 s2v = *(const float4*)&sh[rr + 2][k4 * 4];
            float4 s3v = *(const float4*)&sh[rr + 3][k4 * 4];
            float w0 = w[k4 * 4], w1 = w[k4 * 4 + 1], w2 = w[k4 * 4 + 2], w3 = w[k4 * 4 + 3];
            a0 = fmaf(s0v.x, w0, a0); a0 = fmaf(s0v.y, w1, a0); a0 = fmaf(s0v.z, w2, a0); a0 = fmaf(s0v.w, w3, a0);
            a1 = fmaf(s1v.x, w0, a1); a1 = fmaf(s1v.y, w1, a1); a1 = fmaf(s1v.z, w2, a1); a1 = fmaf(s1v.w, w3, a1);
            a2 = fmaf(s2v.x, w0, a2); a2 = fmaf(s2v.y, w1, a2); a2 = fmaf(s2v.z, w2, a2); a2 = fmaf(s2v.w, w3, a2);
            a3 = fmaf(s3v.x, w0, a3); a3 = fmaf(s3v.y, w1, a3); a3 = fmaf(s3v.z, w2, a3); a3 = fmaf(s3v.w, w3, a3);
        }
        base[(rr + 0) * DHEAD] = a0;
        base[(rr + 1) * DHEAD] = a1;
        base[(rr + 2) * DHEAD] = a2;
        base[(rr + 3) * DHEAD] = a3;
    }
}

// ---------------------------------------------------------------------------
// K2: per-(b,h,d) mean / rstd over s for q and k.
// ---------------------------------------------------------------------------
__global__ void stats_kernel() {
    int bh = blockIdx.x;
    int qk = blockIdx.y;
    const float* src = ((qk == 0) ? g_q : g_k) + bh * S * DHEAD;
    int lane = threadIdx.x & 31;
    int warp = threadIdx.x >> 5;

    float sum = 0.f, ss = 0.f;
    for (int s = warp; s < S; s += 8) {
        float v = src[s * DHEAD + lane];
        sum += v;
        ss = fmaf(v, v, ss);
    }
    __shared__ float shs[8][32], shss[8][32];
    shs[warp][lane] = sum;
    shss[warp][lane] = ss;
    __syncthreads();
    if (warp == 0) {
        float t = 0.f, t2 = 0.f;
#pragma unroll
        for (int w = 0; w < 8; w++) { t += shs[w][lane]; t2 += shss[w][lane]; }
        float mean = t * (1.f / (float)S);
        float var  = t2 * (1.f / (float)S) - mean * mean;
        g_mean[qk][bh][lane] = mean;
        g_rstd[qk][bh][lane] = rsqrtf(var + EPS);
    }
}

// ---------------------------------------------------------------------------
// K3: flash attention. QK^T: 3xBF16 (hi/lo split) m16n8k16 MMAs.
// PV: tf32 m16n8k8 (unchanged). Block: 4 warps x 32 queries = 128 queries.
// Key tiles of 64, two 32-key halves. Register double-buffered tile loads.
// khb/klb: bf16x2-packed K hi/lo, uint32 pitch 20 (conflict-free fragments).
// ---------------------------------------------------------------------------
#define KT 64
#define KBP 20
#define VP 40
#define PP 36
__global__ __launch_bounds__(128) void attn_mma_kernel() {
    __shared__ uint32_t khb[KT][KBP];    // K hi, bf16x2 by dim pairs
    __shared__ uint32_t klb[KT][KBP];    // K lo residual, bf16x2
    __shared__ float vsh[KT][VP];        // V (tf32)
    __shared__ float psh[4][32][PP];     // per-warp P (32 queries x 32 keys)
    __shared__ float kscale[DHEAD], kbias[DHEAD];

    int bh   = blockIdx.y;
    int tid  = threadIdx.x;
    int warp = tid >> 5;
    int lane = tid & 31;
    int gid  = lane >> 2;            // 0..7
    int tig  = lane & 3;             // 0..3

    const float* qp = g_q + bh * S * DHEAD;
    const float4* kp4 = (const float4*)(g_k + bh * S * DHEAD);
    const float4* vp4 = (const float4*)(g_v + bh * S * DHEAD);

    if (tid < DHEAD) {
        float mu = g_mean[1][bh][tid], rs = g_rstd[1][bh][tid];
        kscale[tid] = rs;
        kbias[tid]  = -mu * rs;
    }
    __syncthreads();

    // -------- Q fragments: bf16 hi/lo, m16n8k16 A layout --------
    // qfh[rb][ks][0]: row gid,   cols ks*16+tig*2,+1
    //            [1]: row gid+8, same cols
    //            [2]: row gid,   cols ks*16+8+tig*2,+1
    //            [3]: row gid+8, same cols
    int q0 = blockIdx.x * 128 + warp * 32;
    uint32_t qfh[2][2][4], qfl[2][2][4];
#pragma unroll
    for (int rb = 0; rb < 2; rb++) {
#pragma unroll
        for (int ks = 0; ks < 2; ks++) {
#pragma unroll
            for (int rr = 0; rr < 4; rr++) {
                int row = q0 + rb * 16 + gid + (rr & 1) * 8;
                int c   = ks * 16 + (rr >> 1) * 8 + tig * 2;
                float mu0 = g_mean[0][bh][c],     rs0 = g_rstd[0][bh][c] * SCALE;
                float mu1 = g_mean[0][bh][c + 1], rs1 = g_rstd[0][bh][c + 1] * SCALE;
                float x = (qp[row * DHEAD + c]     - mu0) * rs0;
                float y = (qp[row * DHEAD + c + 1] - mu1) * rs1;
                uint32_t hp = bf16x2_rn(x, y);
                qfh[rb][ks][rr] = hp;
                qfl[rb][ks][rr] = bf16x2_rn(x - bf_lo_f(hp), y - bf_hi_f(hp));
            }
        }
    }

    float oacc0[4][4], oacc1[4][4];
#pragma unroll
    for (int i = 0; i < 4; i++)
#pragma unroll
        for (int j = 0; j < 4; j++) { oacc0[i][j] = 0.f; oacc1[i][j] = 0.f; }
    float m0 = -1e30f, m1 = -1e30f, m2 = -1e30f, m3 = -1e30f;
    float l0 = 0.f, l1 = 0.f, l2 = 0.f, l3 = 0.f;

    // -------- prologue: load tile 0 into registers --------
    float4 kreg[4], vreg[4];
#pragma unroll
    for (int i = 0; i < 4; i++) {
        kreg[i] = kp4[tid + i * 128];
        vreg[i] = vp4[tid + i * 128];
    }

    for (int j0 = 0; j0 < S; j0 += KT) {
        __syncthreads();
        // convert + store the registers holding tile j0
#pragma unroll
        for (int i = 0; i < 4; i++) {
            int idx = tid + i * 128;     // 0..511
            int j   = idx >> 3;
            int d4  = (idx & 7) * 4;
            float4 kk = kreg[i];
            float4 vv = vreg[i];
            float n0 = fmaf(kk.x, kscale[d4 + 0], kbias[d4 + 0]);
            float n1 = fmaf(kk.y, kscale[d4 + 1], kbias[d4 + 1]);
            float n2 = fmaf(kk.z, kscale[d4 + 2], kbias[d4 + 2]);
            float n3 = fmaf(kk.w, kscale[d4 + 3], kbias[d4 + 3]);
            uint32_t h01 = bf16x2_rn(n0, n1);
            uint32_t h23 = bf16x2_rn(n2, n3);
            uint32_t l01 = bf16x2_rn(n0 - bf_lo_f(h01), n1 - bf_hi_f(h01));
            uint32_t l23 = bf16x2_rn(n2 - bf_lo_f(h23), n3 - bf_hi_f(h23));
            int col = d4 >> 1;           // even pair index
            *(uint2*)&khb[j][col] = make_uint2(h01, h23);
            *(uint2*)&klb[j][col] = make_uint2(l01, l23);
            vsh[j][d4 + 0] = tf32r(vv.x);
            vsh[j][d4 + 1] = tf32r(vv.y);
            vsh[j][d4 + 2] = tf32r(vv.z);
            vsh[j][d4 + 3] = tf32r(vv.w);
        }
        __syncthreads();

        // issue next tile's loads now — they complete during compute below
        if (j0 + KT < S) {
            int base4 = ((j0 + KT) * DHEAD) >> 2;
#pragma unroll
            for (int i = 0; i < 4; i++) {
                kreg[i] = kp4[base4 + tid + i * 128];
                vreg[i] = vp4[base4 + tid + i * 128];
            }
        }

#pragma unroll
        for (int hh = 0; hh < 2; hh++) {
            // -------- QK^T: 32x32 scores, 3xBF16 m16n8k16 --------
            float sc0[4][4], sc1[4][4];
#pragma unroll
            for (int nt = 0; nt < 4; nt++) {
#pragma unroll
                for (int j = 0; j < 4; j++) { sc0[nt][j] = 0.f; sc1[nt][j] = 0.f; }
                int r = hh * 32 + nt * 8 + gid;
#pragma unroll
                for (int ks = 0; ks < 2; ks++) {
                    uint32_t bh0 = khb[r][ks * 8 + tig];
                    uint32_t bh1 = khb[r][ks * 8 + 4 + tig];
                    uint32_t bl0 = klb[r][ks * 8 + tig];
                    uint32_t bl1 = klb[r][ks * 8 + 4 + tig];
                    mma_bf16(sc0[nt], qfh[0][ks], bh0, bh1, sc0[nt]);
                    mma_bf16(sc0[nt], qfh[0][ks], bl0, bl1, sc0[nt]);
                    mma_bf16(sc0[nt], qfl[0][ks], bh0, bh1, sc0[nt]);
                    mma_bf16(sc1[nt], qfh[1][ks], bh0, bh1, sc1[nt]);
                    mma_bf16(sc1[nt], qfh[1][ks], bl0, bl1, sc1[nt]);
                    mma_bf16(sc1[nt], qfl[1][ks], bh0, bh1, sc1[nt]);
                }
            }

            // -------- online softmax (4 row groups) --------
            float tm0 = -1e30f, tm1 = -1e30f, tm2 = -1e30f, tm3 = -1e30f;
#pragma unroll
            for (int nt = 0; nt < 4; nt++) {
                tm0 = fmaxf(tm0, fmaxf(sc0[nt][0], sc0[nt][1]));
                tm1 = fmaxf(tm1, fmaxf(sc0[nt][2], sc0[nt][3]));
                tm2 = fmaxf(tm2, fmaxf(sc1[nt][0], sc1[nt][1]));
                tm3 = fmaxf(tm3, fmaxf(sc1[nt][2], sc1[nt][3]));
            }
            tm0 = fmaxf(tm0, __shfl_xor_sync(0xffffffffu, tm0, 1));
            tm0 = fmaxf(tm0, __shfl_xor_sync(0xffffffffu, tm0, 2));
            tm1 = fmaxf(tm1, __shfl_xor_sync(0xffffffffu, tm1, 1));
            tm1 = fmaxf(tm1, __shfl_xor_sync(0xffffffffu, tm1, 2));
            tm2 = fmaxf(tm2, __shfl_xor_sync(0xffffffffu, tm2, 1));
            tm2 = fmaxf(tm2, __shfl_xor_sync(0xffffffffu, tm2, 2));
            tm3 = fmaxf(tm3, __shfl_xor_sync(0xffffffffu, tm3, 1));
            tm3 = fmaxf(tm3, __shfl_xor_sync(0xffffffffu, tm3, 2));

            if (tm0 > m0) {
                float corr = __expf(m0 - tm0); m0 = tm0; l0 *= corr;
#pragma unroll
                for (int nt = 0; nt < 4; nt++) { oacc0[nt][0] *= corr; oacc0[nt][1] *= corr; }
            }
            if (tm1 > m1) {
                float corr = __expf(m1 - tm1); m1 = tm1; l1 *= corr;
#pragma unroll
                for (int nt = 0; nt < 4; nt++) { oacc0[nt][2] *= corr; oacc0[nt][3] *= corr; }
            }
            if (tm2 > m2) {
                float corr = __expf(m2 - tm2); m2 = tm2; l2 *= corr;
#pragma unroll
                for (int nt = 0; nt < 4; nt++) { oacc1[nt][0] *= corr; oacc1[nt][1] *= corr; }
            }
            if (tm3 > m3) {
                float corr = __expf(m3 - tm3); m3 = tm3; l3 *= corr;
#pragma unroll
                for (int nt = 0; nt < 4; nt++) { oacc1[nt][2] *= corr; oacc1[nt][3] *= corr; }
            }

#pragma unroll
            for (int nt = 0; nt < 4; nt++) {
                float p0 = tf32r(__expf(sc0[nt][0] - m0));
                float p1 = tf32r(__expf(sc0[nt][1] - m0));
                float p2 = tf32r(__expf(sc0[nt][2] - m1));
                float p3 = tf32r(__expf(sc0[nt][3] - m1));
                l0 += p0 + p1; l1 += p2 + p3;
                *(float2*)&psh[warp][gid][nt * 8 + 2 * tig]      = make_float2(p0, p1);
                *(float2*)&psh[warp][gid + 8][nt * 8 + 2 * tig]  = make_float2(p2, p3);
                float p4 = tf32r(__expf(sc1[nt][0] - m2));
                float p5 = tf32r(__expf(sc1[nt][1] - m2));
                float p6 = tf32r(__expf(sc1[nt][2] - m3));
                float p7 = tf32r(__expf(sc1[nt][3] - m3));
                l2 += p4 + p5; l3 += p6 + p7;
                *(float2*)&psh[warp][gid + 16][nt * 8 + 2 * tig] = make_float2(p4, p5);
                *(float2*)&psh[warp][gid + 24][nt * 8 + 2 * tig] = make_float2(p6, p7);
            }
            __syncwarp();

            // -------- P @ V : 32 keys of this half (tf32) --------
#pragma unroll
            for (int ks2 = 0; ks2 < 4; ks2++) {
                uint32_t a0[4], a1[4];
                a0[0] = __float_as_uint(psh[warp][gid][ks2 * 8 + tig]);
                a0[1] = __float_as_uint(psh[warp][gid + 8][ks2 * 8 + tig]);
                a0[2] = __float_as_uint(psh[warp][gid][ks2 * 8 + tig + 4]);
                a0[3] = __float_as_uint(psh[warp][gid + 8][ks2 * 8 + tig + 4]);
                a1[0] = __float_as_uint(psh[warp][gid + 16][ks2 * 8 + tig]);
                a1[1] = __float_as_uint(psh[warp][gid + 24][ks2 * 8 + tig]);
                a1[2] = __float_as_uint(psh[warp][gid + 16][ks2 * 8 + tig + 4]);
                a1[3] = __float_as_uint(psh[warp][gid + 24][ks2 * 8 + tig + 4]);
                int vr = hh * 32 + ks2 * 8 + tig;
#pragma unroll
                for (int nt2 = 0; nt2 < 4; nt2++) {
                    uint32_t b0 = __float_as_uint(vsh[vr][nt2 * 8 + gid]);
                    uint32_t b1 = __float_as_uint(vsh[vr + 4][nt2 * 8 + gid]);
                    mma_tf32(oacc0[nt2], a0, b0, b1, oacc0[nt2]);
                    mma_tf32(oacc1[nt2], a1, b0, b1, oacc1[nt2]);
                }
            }
            __syncwarp();
        }
    }

    // -------- reduce denominators across the 4-lane group --------
    l0 += __shfl_xor_sync(0xffffffffu, l0, 1);
    l0 += __shfl_xor_sync(0xffffffffu, l0, 2);
    l1 += __shfl_xor_sync(0xffffffffu, l1, 1);
    l1 += __shfl_xor_sync(0xffffffffu, l1, 2);
    l2 += __shfl_xor_sync(0xffffffffu, l2, 1);
    l2 += __shfl_xor_sync(0xffffffffu, l2, 2);
    l3 += __shfl_xor_sync(0xffffffffu, l3, 1);
    l3 += __shfl_xor_sync(0xffffffffu, l3, 2);

    // -------- epilogue --------
    float inv0 = 1.f / l0, inv1 = 1.f / l1, inv2 = 1.f / l2, inv3 = 1.f / l3;
    int bb = bh >> 2, h = bh & 3;
    float* op0 = g_o + ((bb * S + q0 + gid)      * HEADS + h) * DHEAD;
    float* op1 = g_o + ((bb * S + q0 + gid + 8)  * HEADS + h) * DHEAD;
    float* op2 = g_o + ((bb * S + q0 + gid + 16) * HEADS + h) * DHEAD;
    float* op3 = g_o + ((bb * S + q0 + gid + 24) * HEADS + h) * DHEAD;
#pragma unroll
    for (int nt2 = 0; nt2 < 4; nt2++) {
        int c = nt2 * 8 + 2 * tig;
        *(float2*)(op0 + c) = make_float2(oacc0[nt2][0] * inv0, oacc0[nt2][1] * inv0);
        *(float2*)(op1 + c) = make_float2(oacc0[nt2][2] * inv1, oacc0[nt2][3] * inv1);
        *(float2*)(op2 + c) = make_float2(oacc1[nt2][0] * inv2, oacc1[nt2][1] * inv2);
        *(float2*)(op3 + c) = make_float2(oacc1[nt2][2] * inv3, oacc1[nt2][3] * inv3);
    }
}

// ---------------------------------------------------------------------------
// K4: out = o @ w_out + b_out
// ---------------------------------------------------------------------------
__global__ void out_kernel(const float* __restrict__ w_out,
                           const float* __restrict__ b_out,
                           float* __restrict__ out) {
    __shared__ float sh[HIDDEN];
    int row = blockIdx.x;
    int c   = threadIdx.x;           // 0..63
    sh[c]       = g_o[row * HIDDEN + c];
    sh[c + 64]  = g_o[row * HIDDEN + 64 + c];
    __syncthreads();

    float acc = b_out[c];
#pragma unroll
    for (int k = 0; k < HIDDEN; k++)
        acc = fmaf(sh[k], w_out[k * DIM + c], acc);
    out[row * DIM + c] = acc;
}

// ---------------------------------------------------------------------------
extern "C" void kernel_launch(void* const* d_in, const int* in_sizes, int n_in,
                              void* d_out, int out_size) {
    const float* inp   = (const float*)d_in[0];
    const float* w_qkv = (const float*)d_in[1];
    const float* w_out = (const float*)d_in[2];
    const float* b_out = (const float*)d_in[3];
    float* out = (float*)d_out;

    qkv_kernel<<<NROWS / QR, 384>>>(inp, w_qkv);
    stats_kernel<<<dim3(BH, 2), 256>>>();
    attn_mma_kernel<<<dim3(S / 128, BH), 128>>>();
    out_kernel<<<NROWS, 64>>>(w_out, b_out, out);
}